// round 2
// baseline (speedup 1.0000x reference)
#include <cuda_runtime.h>
#include <cstdint>

#define BB 256
#define TT 1024
#define EE 32
#define HH 64
#define GG 256          // 4*H
#define VV 96
#define NROWS (BB*TT)   // 262144
#define NLOGITS (NROWS*VV)

typedef unsigned long long u64;

// ---------------- scratch (device globals: no allocation allowed) ----------
__device__ float  g_proj[VV][GG];                 // fused (W_ih @ emb[v]) + b_ih + b_hh
__device__ float2 g_W2[128][HH];                  // paired W_hh rows: (W[2j][k], W[2j+1][k])
__device__ float  g_hseq[(size_t)NROWS * HH];     // 64 MB hidden-state sequence
__device__ double g_loss;

// ---------------- f32x2 helpers -------------------------------------------
__device__ __forceinline__ void ffma2(u64 &d, u64 a, u64 b) {
    asm("fma.rn.f32x2 %0, %1, %2, %0;" : "+l"(d) : "l"(a), "l"(b));
}
__device__ __forceinline__ u64 fadd2(u64 a, u64 b) {
    u64 d; asm("add.rn.f32x2 %0, %1, %2;" : "=l"(d) : "l"(a), "l"(b)); return d;
}
__device__ __forceinline__ u64 f2_pack(float lo, float hi) {
    u64 r; asm("mov.b64 %0, {%1, %2};" : "=l"(r) : "f"(lo), "f"(hi)); return r;
}
__device__ __forceinline__ u64 f2_dup(float x) {
    u64 r; asm("mov.b64 %0, {%1, %1};" : "=l"(r) : "f"(x)); return r;
}
__device__ __forceinline__ void f2_unpack(u64 v, float &a, float &b) {
    asm("mov.b64 {%0, %1}, %2;" : "=f"(a), "=f"(b) : "l"(v));
}

// activations: exp-based (2-ulp __expf) — accuracy safe vs 1e-3, saturates correctly
__device__ __forceinline__ float sigm(float x)   { return 1.0f / (1.0f + __expf(-x)); }
__device__ __forceinline__ float tanh_a(float x) { return 1.0f - 2.0f / (1.0f + __expf(2.0f * x)); }

// ---------------- kernel 1: prep (proj table + paired weights + zero loss) -
__global__ void prep_kernel(const float* __restrict__ emb, const float* __restrict__ W_ih,
                            const float* __restrict__ W_hh, const float* __restrict__ b_ih,
                            const float* __restrict__ b_hh)
{
    int t = blockIdx.x * blockDim.x + threadIdx.x;
    if (t < VV * GG) {
        int v = t / GG, g = t % GG;
        float s = b_ih[g] + b_hh[g];
        #pragma unroll
        for (int e = 0; e < EE; e++) s += W_ih[g * EE + e] * emb[v * EE + e];
        g_proj[v][g] = s;
    }
    if (t < 128 * HH) {
        int j = t / HH, k = t % HH;
        g_W2[j][k] = make_float2(W_hh[(2 * j) * HH + k], W_hh[(2 * j + 1) * HH + k]);
    }
    if (t == 0) g_loss = 0.0;
}

// ---------------- kernel 2: LSTM scan (the critical path) ------------------
// 128 blocks x 256 threads; block handles 2 batch lanes (half = tid>>7).
// Thread j (0..127) owns gate pair (2j, 2j+1) of its lane. W_hh pairs live in
// 128 registers. h kept as duplicated f32x2 pairs in SMEM -> inner loop is
// LDS.128 (broadcast) + 2x fma.rn.f32x2, two accumulator chains.
__global__ __launch_bounds__(256, 1) void lstm_kernel(const int* __restrict__ idx)
{
    __shared__ __align__(16) u64 sh_h2[2][HH];    // h duplicated pairs per lane
    __shared__ float sh_gates[2][GG];             // activated gates i|f|g|o

    int tid  = threadIdx.x;
    int half = tid >> 7;            // 0/1: which batch lane
    int j    = tid & 127;           // gate-pair index
    int b    = blockIdx.x * 2 + half;
    const int* idx_b = idx + (size_t)b * TT;

    // weights into registers (64 x u64 = 128 regs)
    u64 w[HH];
    {
        const u64* wp = (const u64*)g_W2[j];
        #pragma unroll
        for (int k = 0; k < HH; k++) w[k] = wp[k];
    }
    if (tid < 2 * HH) sh_h2[tid >> 6][tid & 63] = 0ull;

    float c_lo = 0.f, c_hi = 0.f;                 // cell state (updater threads)
    int  gtype  = j >> 5;                         // 0:i 1:f 2:g 3:o (uniform per warp)
    bool is_upd = ((j & 3) == 0);                 // updaters spread over all SMSPs
    int  u      = j >> 2;                         // hidden-unit pair 2u,2u+1
    float* hout = g_hseq + (size_t)b * TT * HH + 2 * u;

    int id_nxt = idx_b[1];
    u64 xp_cur = *(const u64*)&g_proj[idx_b[0]][2 * j];
    __syncthreads();

    for (int t = 0; t < TT; t++) {
        // prefetch next xp (uses idx known one step ahead) + idx two ahead
        u64 xp_pf = 0ull; int id_pf = 0;
        if (t + 1 < TT) xp_pf = *(const u64*)&g_proj[id_nxt][2 * j];
        if (t + 2 < TT) id_pf = idx_b[t + 2];

        // gates_pre = xp + W_hh * h   (two FFMA2 chains)
        u64 acc0 = xp_cur, acc1 = 0ull;
        const ulonglong2* h4 = (const ulonglong2*)sh_h2[half];
        #pragma unroll
        for (int kk = 0; kk < HH / 2; kk++) {
            ulonglong2 hh = h4[kk];               // LDS.128, warp-broadcast
            ffma2(acc0, hh.x, w[2 * kk]);
            ffma2(acc1, hh.y, w[2 * kk + 1]);
        }
        u64 gsum = fadd2(acc0, acc1);
        float glo, ghi; f2_unpack(gsum, glo, ghi);
        float alo, ahi;
        if (gtype == 2) { alo = tanh_a(glo); ahi = tanh_a(ghi); }
        else            { alo = sigm(glo);   ahi = sigm(ghi);  }
        *(float2*)&sh_gates[half][2 * j] = make_float2(alo, ahi);
        __syncthreads();

        if (is_upd) {
            float2 iv = *(const float2*)&sh_gates[half][      2 * u];
            float2 fv = *(const float2*)&sh_gates[half][ 64 + 2 * u];
            float2 gv = *(const float2*)&sh_gates[half][128 + 2 * u];
            float2 ov = *(const float2*)&sh_gates[half][192 + 2 * u];
            c_lo = fmaf(fv.x, c_lo, iv.x * gv.x);
            c_hi = fmaf(fv.y, c_hi, iv.y * gv.y);
            float hlo = ov.x * tanh_a(c_lo);
            float hhi = ov.y * tanh_a(c_hi);
            sh_h2[half][2 * u]     = f2_pack(hlo, hlo);   // duplicated pairs
            sh_h2[half][2 * u + 1] = f2_pack(hhi, hhi);
            *(float2*)&hout[(size_t)t * HH] = make_float2(hlo, hhi);
        }
        __syncthreads();
        xp_cur = xp_pf;
        id_nxt = id_pf;
    }
}

// ---------------- kernel 3: output projection + log-softmax loss -----------
// Block tile: 64 rows x 96 cols, 256 threads. Thread (tr=tid/32, tc=tid%32)
// owns 4 row-pairs x 3 cols as f32x2 accumulators (24 outputs). h staged
// transposed in SMEM so row-pairs are contiguous 8B; w staged transposed
// (pad 97 -> conflict-free). Each warp owns 8 complete rows -> shuffle
// log-softmax, red.add.f64 loss partials.
__global__ __launch_bounds__(256) void outproj_kernel(const float* __restrict__ fc_w,
                                                      const float* __restrict__ fc_b,
                                                      const int*   __restrict__ targets,
                                                      float*       __restrict__ out)
{
    __shared__ float wS[HH][97];                  // wS[k][v] = fc_w[v][k]
    __shared__ __align__(16) float hS[HH][66];    // hS[k][r] (pad 66 keeps 8B align)
    __shared__ float bS[VV];

    int tid = threadIdx.x;
    for (int i = tid; i < VV * HH; i += 256) { int v = i >> 6, k = i & 63; wS[k][v] = fc_w[i]; }
    if (tid < VV) bS[tid] = fc_b[tid];

    int rbase = blockIdx.x * 64;
    for (int i4 = tid; i4 < 64 * 16; i4 += 256) {
        int r = i4 >> 4, k4 = (i4 & 15) << 2;
        float4 hv = *(const float4*)&g_hseq[((size_t)(rbase + r)) * HH + k4];
        hS[k4][r] = hv.x; hS[k4 + 1][r] = hv.y; hS[k4 + 2][r] = hv.z; hS[k4 + 3][r] = hv.w;
    }
    __syncthreads();

    int tc = tid & 31, tr = tid >> 5;
    int c0 = 3 * tc;

    u64 acc[4][3];
    #pragma unroll
    for (int p = 0; p < 4; p++)
        #pragma unroll
        for (int q = 0; q < 3; q++) acc[p][q] = 0ull;

    #pragma unroll 4
    for (int k = 0; k < HH; k++) {
        u64 b0 = f2_dup(wS[k][c0]);
        u64 b1 = f2_dup(wS[k][c0 + 1]);
        u64 b2 = f2_dup(wS[k][c0 + 2]);
        #pragma unroll
        for (int p = 0; p < 4; p++) {
            u64 a = *(const u64*)&hS[k][(tr * 4 + p) * 2];   // (h[r0][k], h[r1][k])
            ffma2(acc[p][0], a, b0);
            ffma2(acc[p][1], a, b1);
            ffma2(acc[p][2], a, b2);
        }
    }

    float lg[8][3];
    #pragma unroll
    for (int p = 0; p < 4; p++)
        #pragma unroll
        for (int q = 0; q < 3; q++) {
            float lo, hi; f2_unpack(acc[p][q], lo, hi);
            lg[2 * p][q]     = lo + bS[c0 + q];
            lg[2 * p + 1][q] = hi + bS[c0 + q];
        }

    float lacc = 0.f;
    #pragma unroll
    for (int rr = 0; rr < 8; rr++) {
        int row = tr * 8 + rr;
        float v0 = lg[rr][0], v1 = lg[rr][1], v2 = lg[rr][2];
        float* gout = out + (size_t)(rbase + row) * VV + c0;
        gout[0] = v0; gout[1] = v1; gout[2] = v2;

        float m = fmaxf(v0, fmaxf(v1, v2));
        #pragma unroll
        for (int off = 16; off; off >>= 1) m = fmaxf(m, __shfl_xor_sync(0xffffffffu, m, off));
        float s = __expf(v0 - m) + __expf(v1 - m) + __expf(v2 - m);
        #pragma unroll
        for (int off = 16; off; off >>= 1) s += __shfl_xor_sync(0xffffffffu, s, off);

        int tgt = targets[rbase + row];
        bool own = (tgt >= c0) && (tgt < c0 + 3);
        float lt = (tgt == c0) ? v0 : ((tgt == c0 + 1) ? v1 : v2);
        lacc += own ? (m + __logf(s) - lt) : 0.f;
    }
    #pragma unroll
    for (int off = 16; off; off >>= 1) lacc += __shfl_xor_sync(0xffffffffu, lacc, off);
    if (tc == 0) atomicAdd(&g_loss, (double)lacc);
}

__global__ void loss_fin_kernel(float* __restrict__ out)
{
    out[NLOGITS] = (float)(g_loss * (1.0 / (double)NROWS));
}

// ---------------- launch ----------------------------------------------------
extern "C" void kernel_launch(void* const* d_in, const int* in_sizes, int n_in,
                              void* d_out, int out_size)
{
    const int*   idx     = (const int*)  d_in[0];
    const int*   targets = (const int*)  d_in[1];
    const float* emb     = (const float*)d_in[2];
    const float* W_ih    = (const float*)d_in[3];
    const float* W_hh    = (const float*)d_in[4];
    const float* b_ih    = (const float*)d_in[5];
    const float* b_hh    = (const float*)d_in[6];
    const float* fc_w    = (const float*)d_in[7];
    const float* fc_b    = (const float*)d_in[8];
    float* out = (float*)d_out;

    prep_kernel<<<96, 256>>>(emb, W_ih, W_hh, b_ih, b_hh);
    lstm_kernel<<<BB / 2, 256>>>(idx);
    outproj_kernel<<<NROWS / 64, 256>>>(fc_w, fc_b, targets, out);
    if (out_size > NLOGITS) loss_fin_kernel<<<1, 1>>>(out);
}

// round 3
// speedup vs baseline: 1.0718x; 1.0718x over previous
#include <cuda_runtime.h>
#include <cstdint>

#define BB 256
#define TT 1024
#define EE 32
#define HH 64
#define GG 256          // 4*H
#define VV 96
#define NROWS (BB*TT)   // 262144
#define NLOGITS (NROWS*VV)

typedef unsigned long long u64;

// ---------------- scratch (device globals: no allocation allowed) ----------
// Pairing: thread j owns gate rows (j, 128+j):
//   j in [0,64):   (i[j],  g[j])
//   j in [64,128): (f[j-64], o[j-64])
__device__ float2 g_projP[VV][128];               // fused (W_ih@emb[v] + b_ih + b_hh), paired
__device__ float2 g_W2[128][HH];                  // paired W_hh rows (j, 128+j)
__device__ float  g_hseq[(size_t)NROWS * HH];     // 64 MB hidden-state sequence
__device__ double g_loss;

// ---------------- f32x2 helpers -------------------------------------------
__device__ __forceinline__ void ffma2(u64 &d, u64 a, u64 b) {
    asm("fma.rn.f32x2 %0, %1, %2, %0;" : "+l"(d) : "l"(a), "l"(b));
}
__device__ __forceinline__ u64 fadd2(u64 a, u64 b) {
    u64 d; asm("add.rn.f32x2 %0, %1, %2;" : "=l"(d) : "l"(a), "l"(b)); return d;
}
__device__ __forceinline__ u64 f2_dup(float x) {
    u64 r; asm("mov.b64 %0, {%1, %1};" : "=l"(r) : "f"(x)); return r;
}
__device__ __forceinline__ void f2_unpack(u64 v, float &a, float &b) {
    asm("mov.b64 {%0, %1}, %2;" : "=f"(a), "=f"(b) : "l"(v));
}

// activations: exp-based (2-ulp __expf) — proven rel_err 2.6e-7 in R2
__device__ __forceinline__ float sigm(float x)   { return 1.0f / (1.0f + __expf(-x)); }
__device__ __forceinline__ float tanh_a(float x) { return 1.0f - 2.0f / (1.0f + __expf(2.0f * x)); }

// ---------------- kernel 1: prep (paired proj table + paired weights) ------
__global__ void prep_kernel(const float* __restrict__ emb, const float* __restrict__ W_ih,
                            const float* __restrict__ W_hh, const float* __restrict__ b_ih,
                            const float* __restrict__ b_hh)
{
    int t = blockIdx.x * blockDim.x + threadIdx.x;
    if (t < VV * 128) {
        int v = t >> 7, j = t & 127;
        int ra = j, rb = 128 + j;
        float sa = b_ih[ra] + b_hh[ra];
        float sb = b_ih[rb] + b_hh[rb];
        #pragma unroll
        for (int e = 0; e < EE; e++) {
            float ev = emb[v * EE + e];
            sa += W_ih[ra * EE + e] * ev;
            sb += W_ih[rb * EE + e] * ev;
        }
        g_projP[v][j] = make_float2(sa, sb);
    }
    if (t < 128 * HH) {
        int j = t >> 6, k = t & 63;
        g_W2[j][k] = make_float2(W_hh[j * HH + k], W_hh[(128 + j) * HH + k]);
    }
    if (t == 0) g_loss = 0.0;
}

// ---------------- kernel 2: LSTM scan (critical path) ----------------------
// 256 blocks x 128 threads, one batch lane per block (~2 blocks/SM so two
// independent lanes overlap each other's serial phases). Thread j owns gate
// rows (j, 128+j) as one f32x2 chain against W pairs held in 128 registers.
// h kept as duplicated f32x2 in SMEM -> inner loop = LDS.128 + 2x fma.rn.f32x2.
__global__ __launch_bounds__(128) void lstm_kernel(const int* __restrict__ idx)
{
    __shared__ __align__(16) u64 sh_h2[HH];       // duplicated h pairs
    __shared__ float sh_p[HH];                    // p[u] = sigm(i)*tanh(g)
    __shared__ int   sh_idx[TT];

    int j = threadIdx.x;                          // 0..127
    int b = blockIdx.x;

    // stage idx row in smem (coalesced, once)
    {
        const int4* src = (const int4*)(idx + (size_t)b * TT);
        int4* dst = (int4*)sh_idx;
        #pragma unroll
        for (int i = j; i < TT / 4; i += 128) dst[i] = src[i];
    }

    // weights into registers (64 x u64 = 128 regs)
    u64 w[HH];
    {
        const u64* wp = (const u64*)g_W2[j];
        #pragma unroll
        for (int k = 0; k < HH; k++) w[k] = wp[k];
    }
    if (j < HH) sh_h2[j] = 0ull;
    float cst = 0.f;                              // cell state (threads j>=64)
    bool is_upd = (j >= 64);
    int  u = j & 63;
    float* hout = g_hseq + (size_t)b * TT * HH + u;

    __syncthreads();

    u64 xp_cur = *(const u64*)&g_projP[sh_idx[0]][j];
    int id_nxt = sh_idx[1];

    for (int t = 0; t < TT; t++) {
        // prefetch next xp (L2-resident 96KB table, hidden under this step)
        u64 xp_pf = *(const u64*)&g_projP[id_nxt][j];
        int id_pf = sh_idx[(t + 2 < TT) ? (t + 2) : (TT - 1)];

        // gate pre-activations: xp + sum_k h[k] * w[k]  (4 FFMA2 chains)
        u64 a0 = xp_cur, a1 = 0ull, a2 = 0ull, a3 = 0ull;
        const ulonglong2* h4 = (const ulonglong2*)sh_h2;
        #pragma unroll
        for (int kk = 0; kk < 16; kk++) {
            ulonglong2 ha = h4[2 * kk];           // LDS.128 broadcast
            ulonglong2 hb = h4[2 * kk + 1];
            ffma2(a0, ha.x, w[4 * kk]);
            ffma2(a1, ha.y, w[4 * kk + 1]);
            ffma2(a2, hb.x, w[4 * kk + 2]);
            ffma2(a3, hb.y, w[4 * kk + 3]);
        }
        u64 gsum = fadd2(fadd2(a0, a1), fadd2(a2, a3));
        float glo, ghi; f2_unpack(gsum, glo, ghi);

        float alo = sigm(glo);                            // i (j<64) or f (j>=64)
        float ahi = is_upd ? sigm(ghi) : tanh_a(ghi);     // o or g
        if (!is_upd) sh_p[u] = alo * ahi;                 // p = sigm(i)*tanh(g)
        __syncthreads();

        if (is_upd) {
            cst = fmaf(alo, cst, sh_p[u]);                // c = f*c + i*g
            float h = ahi * tanh_a(cst);                  // h = o*tanh(c)
            sh_h2[u] = f2_dup(h);
            hout[(size_t)t * HH] = h;                     // coalesced 256B/step
        }
        __syncthreads();

        xp_cur = xp_pf;
        id_nxt = id_pf;
    }
}

// ---------------- kernel 3: output projection + log-softmax loss -----------
__global__ __launch_bounds__(256) void outproj_kernel(const float* __restrict__ fc_w,
                                                      const float* __restrict__ fc_b,
                                                      const int*   __restrict__ targets,
                                                      float*       __restrict__ out)
{
    __shared__ float wS[HH][97];                  // wS[k][v] = fc_w[v][k]
    __shared__ __align__(16) float hS[HH][66];    // hS[k][r] (pad 66 keeps 8B align)
    __shared__ float bS[VV];

    int tid = threadIdx.x;
    for (int i = tid; i < VV * HH; i += 256) { int v = i >> 6, k = i & 63; wS[k][v] = fc_w[i]; }
    if (tid < VV) bS[tid] = fc_b[tid];

    int rbase = blockIdx.x * 64;
    for (int i4 = tid; i4 < 64 * 16; i4 += 256) {
        int r = i4 >> 4, k4 = (i4 & 15) << 2;
        float4 hv = *(const float4*)&g_hseq[((size_t)(rbase + r)) * HH + k4];
        hS[k4][r] = hv.x; hS[k4 + 1][r] = hv.y; hS[k4 + 2][r] = hv.z; hS[k4 + 3][r] = hv.w;
    }
    __syncthreads();

    int tc = tid & 31, tr = tid >> 5;
    int c0 = 3 * tc;

    u64 acc[4][3];
    #pragma unroll
    for (int p = 0; p < 4; p++)
        #pragma unroll
        for (int q = 0; q < 3; q++) acc[p][q] = 0ull;

    #pragma unroll 4
    for (int k = 0; k < HH; k++) {
        u64 b0 = f2_dup(wS[k][c0]);
        u64 b1 = f2_dup(wS[k][c0 + 1]);
        u64 b2 = f2_dup(wS[k][c0 + 2]);
        #pragma unroll
        for (int p = 0; p < 4; p++) {
            u64 a = *(const u64*)&hS[k][(tr * 4 + p) * 2];   // (h[r0][k], h[r1][k])
            ffma2(acc[p][0], a, b0);
            ffma2(acc[p][1], a, b1);
            ffma2(acc[p][2], a, b2);
        }
    }

    float lg[8][3];
    #pragma unroll
    for (int p = 0; p < 4; p++)
        #pragma unroll
        for (int q = 0; q < 3; q++) {
            float lo, hi; f2_unpack(acc[p][q], lo, hi);
            lg[2 * p][q]     = lo + bS[c0 + q];
            lg[2 * p + 1][q] = hi + bS[c0 + q];
        }

    float lacc = 0.f;
    #pragma unroll
    for (int rr = 0; rr < 8; rr++) {
        int row = tr * 8 + rr;
        float v0 = lg[rr][0], v1 = lg[rr][1], v2 = lg[rr][2];
        float* gout = out + (size_t)(rbase + row) * VV + c0;
        gout[0] = v0; gout[1] = v1; gout[2] = v2;

        float m = fmaxf(v0, fmaxf(v1, v2));
        #pragma unroll
        for (int off = 16; off; off >>= 1) m = fmaxf(m, __shfl_xor_sync(0xffffffffu, m, off));
        float s = __expf(v0 - m) + __expf(v1 - m) + __expf(v2 - m);
        #pragma unroll
        for (int off = 16; off; off >>= 1) s += __shfl_xor_sync(0xffffffffu, s, off);

        int tgt = targets[rbase + row];
        bool own = (tgt >= c0) && (tgt < c0 + 3);
        float lt = (tgt == c0) ? v0 : ((tgt == c0 + 1) ? v1 : v2);
        lacc += own ? (m + __logf(s) - lt) : 0.f;
    }
    #pragma unroll
    for (int off = 16; off; off >>= 1) lacc += __shfl_xor_sync(0xffffffffu, lacc, off);
    if (tc == 0) atomicAdd(&g_loss, (double)lacc);
}

__global__ void loss_fin_kernel(float* __restrict__ out)
{
    out[NLOGITS] = (float)(g_loss * (1.0 / (double)NROWS));
}

// ---------------- launch ----------------------------------------------------
extern "C" void kernel_launch(void* const* d_in, const int* in_sizes, int n_in,
                              void* d_out, int out_size)
{
    const int*   idx     = (const int*)  d_in[0];
    const int*   targets = (const int*)  d_in[1];
    const float* emb     = (const float*)d_in[2];
    const float* W_ih    = (const float*)d_in[3];
    const float* W_hh    = (const float*)d_in[4];
    const float* b_ih    = (const float*)d_in[5];
    const float* b_hh    = (const float*)d_in[6];
    const float* fc_w    = (const float*)d_in[7];
    const float* fc_b    = (const float*)d_in[8];
    float* out = (float*)d_out;

    prep_kernel<<<96, 256>>>(emb, W_ih, W_hh, b_ih, b_hh);
    lstm_kernel<<<BB, 128>>>(idx);
    outproj_kernel<<<NROWS / 64, 256>>>(fc_w, fc_b, targets, out);
    if (out_size > NLOGITS) loss_fin_kernel<<<1, 1>>>(out);
}